// round 2
// baseline (speedup 1.0000x reference)
#include <cuda_runtime.h>
#include <cuda_bf16.h>
#include <math.h>

// Problem constants
#define BB 4
#define TT 2048
#define DD 1024
#define HH 16
#define DHH 64

// Scratch buffers (no cudaMalloc allowed)
__device__ float g_qkv[(size_t)BB * TT * 3 * DD];   // (B,T,3D)
__device__ float g_attn[(size_t)BB * TT * DD];      // (B,T,D)

// ---------------------------------------------------------------------------
// SGEMM: C[M,N] = A[M,K] @ B[K,N], all row-major fp32.
// 128x128 block, BK=8, 256 threads, 8x8 register tile per thread.
// M,N,K all divisible by tile dims (8192/3072/1024) -> no bounds checks.
// ---------------------------------------------------------------------------
__global__ __launch_bounds__(256) void sgemm128(const float* __restrict__ A,
                                                const float* __restrict__ B,
                                                float* __restrict__ C,
                                                int M, int N, int K)
{
    const int BM = 128, BN = 128, BK = 8, TM = 8, TN = 8;
    __shared__ float As[BK][BM];
    __shared__ float Bs[BK][BN];

    int tid = threadIdx.x;
    int bx = blockIdx.x;   // N tile
    int by = blockIdx.y;   // M tile

    int trow = tid / 16;   // 0..15
    int tcol = tid % 16;   // 0..15

    // Global load mapping
    int aRow = tid >> 1;            // 0..127
    int aCol = (tid & 1) * 4;       // 0 or 4
    int bRow = tid >> 5;            // 0..7
    int bCol = (tid & 31) * 4;      // 0..124

    const float* Ablk = A + (size_t)(by * BM) * K;
    const float* Bblk = B + bx * BN;

    float acc[TM][TN];
#pragma unroll
    for (int i = 0; i < TM; i++)
#pragma unroll
        for (int j = 0; j < TN; j++) acc[i][j] = 0.f;

    for (int k0 = 0; k0 < K; k0 += BK) {
        float4 a4 = *(const float4*)(Ablk + (size_t)aRow * K + k0 + aCol);
        As[aCol + 0][aRow] = a4.x;
        As[aCol + 1][aRow] = a4.y;
        As[aCol + 2][aRow] = a4.z;
        As[aCol + 3][aRow] = a4.w;
        float4 b4 = *(const float4*)(Bblk + (size_t)(k0 + bRow) * N + bCol);
        *(float4*)&Bs[bRow][bCol] = b4;
        __syncthreads();

#pragma unroll
        for (int kk = 0; kk < BK; ++kk) {
            float af[TM], bf[TN];
            float4 afa = *(const float4*)&As[kk][trow * TM];
            float4 afb = *(const float4*)&As[kk][trow * TM + 4];
            af[0]=afa.x; af[1]=afa.y; af[2]=afa.z; af[3]=afa.w;
            af[4]=afb.x; af[5]=afb.y; af[6]=afb.z; af[7]=afb.w;
            float4 bfa = *(const float4*)&Bs[kk][tcol * TN];
            float4 bfb = *(const float4*)&Bs[kk][tcol * TN + 4];
            bf[0]=bfa.x; bf[1]=bfa.y; bf[2]=bfa.z; bf[3]=bfa.w;
            bf[4]=bfb.x; bf[5]=bfb.y; bf[6]=bfb.z; bf[7]=bfb.w;
#pragma unroll
            for (int i = 0; i < TM; i++)
#pragma unroll
                for (int j = 0; j < TN; j++)
                    acc[i][j] += af[i] * bf[j];
        }
        __syncthreads();
    }

#pragma unroll
    for (int i = 0; i < TM; i++) {
        float* Crow = C + (size_t)(by * BM + trow * TM + i) * N + bx * BN + tcol * TN;
        float4 w0, w1;
        w0.x = acc[i][0]; w0.y = acc[i][1]; w0.z = acc[i][2]; w0.w = acc[i][3];
        w1.x = acc[i][4]; w1.y = acc[i][5]; w1.z = acc[i][6]; w1.w = acc[i][7];
        *(float4*)Crow = w0;
        *(float4*)(Crow + 4) = w1;
    }
}

// ---------------------------------------------------------------------------
// Flash attention (causal). One block per (query_block, b*H+h).
// BM=BN=64, DH=64, 128 threads: thread = (row r = tid/2, half = tid&1).
// Each thread owns 32 output dims of its row; partner exchange via shfl.
// ---------------------------------------------------------------------------
#define ROWPAD 68
#define FLASH_SMEM (4 * 64 * ROWPAD * (int)sizeof(float))   // 69632 B

__global__ __launch_bounds__(128) void flash_attn(const float* __restrict__ qkv,
                                                  float* __restrict__ out)
{
    extern __shared__ float sm[];
    float* Qs = sm;                    // [64][ROWPAD]
    float* Ks = Qs + 64 * ROWPAD;
    float* Vs = Ks + 64 * ROWPAD;
    float* Ps = Vs + 64 * ROWPAD;

    const int T = TT, D = DD, H = HH;
    int qi = blockIdx.x;               // query tile index (0..31)
    int bh = blockIdx.y;               // 0..63
    int b = bh / H, h = bh % H;
    int tid = threadIdx.x;
    int r = tid >> 1;                  // 0..63
    int half = tid & 1;                // 0/1

    const float* qbase = qkv + ((size_t)b * T) * 3 * D + h * DHH;   // +t*3D+d
    const float* kbase = qbase + D;
    const float* vbase = qbase + 2 * D;

    int q0 = qi * 64;

    // Load Q tile (64x64): each thread 8 float4
    {
        int lr = tid >> 1;
        int c0 = (tid & 1) * 32;
        const float4* src = (const float4*)(qbase + (size_t)(q0 + lr) * 3 * D + c0);
        float4* dst = (float4*)(Qs + lr * ROWPAD + c0);
#pragma unroll
        for (int i = 0; i < 8; i++) dst[i] = src[i];
    }

    float m = -INFINITY, l = 0.f;
    float o[32];
#pragma unroll
    for (int i = 0; i < 32; i++) o[i] = 0.f;

    const float LOG2E = 1.44269504088896f;

    for (int j = 0; j <= qi; ++j) {
        int k0 = j * 64;
        __syncthreads();   // previous-iter smem reads done (also covers Q on iter 0)
        {
            int lr = tid >> 1;
            int c0 = (tid & 1) * 32;
            const float4* ksrc = (const float4*)(kbase + (size_t)(k0 + lr) * 3 * D + c0);
            float4* kdst = (float4*)(Ks + lr * ROWPAD + c0);
            const float4* vsrc = (const float4*)(vbase + (size_t)(k0 + lr) * 3 * D + c0);
            float4* vdst = (float4*)(Vs + lr * ROWPAD + c0);
#pragma unroll
            for (int i = 0; i < 8; i++) { kdst[i] = ksrc[i]; vdst[i] = vsrc[i]; }
        }
        __syncthreads();

        // ---- scores: s[cc] = Q[r] . K[half*32+cc] ----
        float s[32];
#pragma unroll
        for (int i = 0; i < 32; i++) s[i] = 0.f;
        const float* qrow = Qs + r * ROWPAD;
#pragma unroll
        for (int d0 = 0; d0 < 64; d0 += 8) {
            float4 qa = *(const float4*)(qrow + d0);
            float4 qb = *(const float4*)(qrow + d0 + 4);
#pragma unroll
            for (int cc = 0; cc < 32; ++cc) {
                const float* krow = Ks + (half * 32 + cc) * ROWPAD + d0;
                float4 ka = *(const float4*)(krow);
                float4 kb = *(const float4*)(krow + 4);
                s[cc] += qa.x * ka.x + qa.y * ka.y + qa.z * ka.z + qa.w * ka.w
                       + qb.x * kb.x + qb.y * kb.y + qb.z * kb.z + qb.w * kb.w;
            }
        }

        // ---- scale + causal mask + online softmax ----
        bool diag = (j == qi);
        float smax = -INFINITY;
#pragma unroll
        for (int cc = 0; cc < 32; ++cc) {
            float v = s[cc] * 0.125f;                  // 1/sqrt(64)
            if (diag && (half * 32 + cc) > r) v = -INFINITY;
            s[cc] = v;
            smax = fmaxf(smax, v);
        }
        smax = fmaxf(smax, __shfl_xor_sync(0xffffffffu, smax, 1));
        float mnew = fmaxf(m, smax);
        float alpha = exp2f((m - mnew) * LOG2E);
        float lsum = 0.f;
#pragma unroll
        for (int cc = 0; cc < 32; ++cc) {
            float p = exp2f((s[cc] - mnew) * LOG2E);
            Ps[r * ROWPAD + half * 32 + cc] = p;
            lsum += p;
        }
        lsum += __shfl_xor_sync(0xffffffffu, lsum, 1);
        l = l * alpha + lsum;
        m = mnew;
#pragma unroll
        for (int i = 0; i < 32; i++) o[i] *= alpha;

        __syncwarp();   // partner's Ps writes visible (partners share a warp)

        // ---- O += P @ V  (this thread: 32 dims at half*32) ----
        const float* prow = Ps + r * ROWPAD;
#pragma unroll
        for (int c0 = 0; c0 < 64; c0 += 8) {
            float4 pa = *(const float4*)(prow + c0);
            float4 pb = *(const float4*)(prow + c0 + 4);
            float p8[8] = {pa.x, pa.y, pa.z, pa.w, pb.x, pb.y, pb.z, pb.w};
#pragma unroll
            for (int i = 0; i < 8; i++) {
                const float4* vr = (const float4*)(Vs + (c0 + i) * ROWPAD + half * 32);
#pragma unroll
                for (int d4 = 0; d4 < 8; ++d4) {
                    float4 vv = vr[d4];
                    o[d4 * 4 + 0] += p8[i] * vv.x;
                    o[d4 * 4 + 1] += p8[i] * vv.y;
                    o[d4 * 4 + 2] += p8[i] * vv.z;
                    o[d4 * 4 + 3] += p8[i] * vv.w;
                }
            }
        }
        __syncwarp();
    }

    // ---- finalize: out[b, q0+r, h*64 + half*32 + *] = o / l ----
    float inv_l = 1.f / l;
    float* dst = out + ((size_t)b * T + q0 + r) * D + h * DHH + half * 32;
#pragma unroll
    for (int d4 = 0; d4 < 8; ++d4) {
        float4 w;
        w.x = o[d4 * 4 + 0] * inv_l;
        w.y = o[d4 * 4 + 1] * inv_l;
        w.z = o[d4 * 4 + 2] * inv_l;
        w.w = o[d4 * 4 + 3] * inv_l;
        *(float4*)(dst + d4 * 4) = w;
    }
}

// ---------------------------------------------------------------------------
extern "C" void kernel_launch(void* const* d_in, const int* in_sizes, int n_in,
                              void* d_out, int out_size)
{
    const float* x    = (const float*)d_in[0];
    // d_in[1] = causal mask (structural; ignored)
    const float* Wqkv = (const float*)d_in[2];
    const float* Wout = (const float*)d_in[3];
    float* out = (float*)d_out;

    float* qkv_ptr  = nullptr;
    float* attn_ptr = nullptr;
    cudaGetSymbolAddress((void**)&qkv_ptr,  g_qkv);
    cudaGetSymbolAddress((void**)&attn_ptr, g_attn);

    cudaFuncSetAttribute(flash_attn, cudaFuncAttributeMaxDynamicSharedMemorySize,
                         FLASH_SMEM);

    const int M = BB * TT;        // 8192
    // 1) QKV projection: (8192,1024) @ (1024,3072)
    {
        dim3 grid(3 * DD / 128, M / 128);
        sgemm128<<<grid, 256>>>(x, Wqkv, qkv_ptr, M, 3 * DD, DD);
    }
    // 2) Flash attention
    {
        dim3 grid(TT / 64, BB * HH);
        flash_attn<<<grid, 128, FLASH_SMEM>>>(qkv_ptr, attn_ptr);
    }
    // 3) Output projection: (8192,1024) @ (1024,1024)
    {
        dim3 grid(DD / 128, M / 128);
        sgemm128<<<grid, 256>>>(attn_ptr, Wout, out, M, DD, DD);
    }
}

// round 6
// speedup vs baseline: 3.4597x; 3.4597x over previous
#include <cuda_runtime.h>
#include <cuda_bf16.h>
#include <math.h>
#include <stdint.h>

// Problem constants
#define BB 4
#define TT 2048
#define DD 1024
#define HH 16
#define DHH 64

// Scratch buffers (no cudaMalloc allowed)
__device__ float g_qkv[(size_t)BB * TT * 3 * DD];   // (B,T,3D)
__device__ float g_attn[(size_t)BB * TT * DD];      // (B,T,D)

// ---------------------------------------------------------------------------
// tf32 helpers
// ---------------------------------------------------------------------------
__device__ __forceinline__ uint32_t tf32u(float x) {
    uint32_t u;
    asm("cvt.rna.tf32.f32 %0, %1;" : "=r"(u) : "f"(x));
    return u;
}
__device__ __forceinline__ float tf32f(float x) {
    return __uint_as_float(tf32u(x));
}

// mma.sync m16n8k8 tf32, fp32 accumulate (C += A*B)
__device__ __forceinline__ void mma_tf32(float* c, const uint32_t* a, const uint32_t* b) {
    asm volatile(
        "mma.sync.aligned.m16n8k8.row.col.f32.tf32.tf32.f32 "
        "{%0,%1,%2,%3}, {%4,%5,%6,%7}, {%8,%9}, {%0,%1,%2,%3};\n"
        : "+f"(c[0]), "+f"(c[1]), "+f"(c[2]), "+f"(c[3])
        : "r"(a[0]), "r"(a[1]), "r"(a[2]), "r"(a[3]), "r"(b[0]), "r"(b[1]));
}

// ---------------------------------------------------------------------------
// GEMM: C[M,N] = A[M,K] @ B[K,N], fp32 in/out, tf32 tensor-core compute.
// Block 128x128, BK=16, 256 threads (8 warps in 4x2), warp tile 32x64.
// M,N,K divisible by tile dims (8192 / 3072|1024 / 1024).
// ---------------------------------------------------------------------------
__global__ __launch_bounds__(256, 2) void gemm_tf32(const float* __restrict__ A,
                                                    const float* __restrict__ B,
                                                    float* __restrict__ C,
                                                    int M, int N, int K)
{
    __shared__ uint32_t As[128][20];   // stride 20 -> conflict-free A-frag LDS
    __shared__ uint32_t Bs[16][136];   // stride 136 (==8 mod 32) -> conflict-free B-frag LDS

    int tid  = threadIdx.x;
    int warp = tid >> 5, lane = tid & 31;
    int g = lane >> 2, t = lane & 3;
    int wm = warp >> 1;          // 0..3
    int wn = warp & 1;           // 0..1
    int bx = blockIdx.x, by = blockIdx.y;

    const float* Ag = A + (size_t)(by * 128) * K;
    const float* Bg = B + bx * 128;

    // global->smem mapping (float4 per slot, 2 slots each for A and B)
    int arow = tid >> 2;            // 0..63 (+64 for second)
    int acol = (tid & 3) * 4;       // 0,4,8,12
    int brow = tid >> 5;            // 0..7 (+8 for second)
    int bcol = (tid & 31) * 4;      // 0..124

    float acc[2][8][4];
#pragma unroll
    for (int mt = 0; mt < 2; mt++)
#pragma unroll
        for (int nt = 0; nt < 8; nt++)
#pragma unroll
            for (int i = 0; i < 4; i++) acc[mt][nt][i] = 0.f;

    // prefetch tile 0
    float4 pa0 = *(const float4*)(Ag + (size_t)arow * K + acol);
    float4 pa1 = *(const float4*)(Ag + (size_t)(arow + 64) * K + acol);
    float4 pb0 = *(const float4*)(Bg + (size_t)brow * N + bcol);
    float4 pb1 = *(const float4*)(Bg + (size_t)(brow + 8) * N + bcol);

    int ntile = K / 16;
    for (int kt = 0; kt < ntile; kt++) {
        // store prefetched tile to smem with tf32 rounding
        As[arow][acol + 0] = tf32u(pa0.x);
        As[arow][acol + 1] = tf32u(pa0.y);
        As[arow][acol + 2] = tf32u(pa0.z);
        As[arow][acol + 3] = tf32u(pa0.w);
        As[arow + 64][acol + 0] = tf32u(pa1.x);
        As[arow + 64][acol + 1] = tf32u(pa1.y);
        As[arow + 64][acol + 2] = tf32u(pa1.z);
        As[arow + 64][acol + 3] = tf32u(pa1.w);
        Bs[brow][bcol + 0] = tf32u(pb0.x);
        Bs[brow][bcol + 1] = tf32u(pb0.y);
        Bs[brow][bcol + 2] = tf32u(pb0.z);
        Bs[brow][bcol + 3] = tf32u(pb0.w);
        Bs[brow + 8][bcol + 0] = tf32u(pb1.x);
        Bs[brow + 8][bcol + 1] = tf32u(pb1.y);
        Bs[brow + 8][bcol + 2] = tf32u(pb1.z);
        Bs[brow + 8][bcol + 3] = tf32u(pb1.w);
        __syncthreads();

        // prefetch next tile
        if (kt + 1 < ntile) {
            const float* An = Ag + (kt + 1) * 16;
            pa0 = *(const float4*)(An + (size_t)arow * K + acol);
            pa1 = *(const float4*)(An + (size_t)(arow + 64) * K + acol);
            const float* Bn = Bg + (size_t)((kt + 1) * 16) * N;
            pb0 = *(const float4*)(Bn + (size_t)brow * N + bcol);
            pb1 = *(const float4*)(Bn + (size_t)(brow + 8) * N + bcol);
        }

        // compute: 2 k-steps of 8
#pragma unroll
        for (int ks = 0; ks < 2; ks++) {
            uint32_t af[2][4];
#pragma unroll
            for (int mt = 0; mt < 2; mt++) {
                int row = wm * 32 + mt * 16;
                af[mt][0] = As[row + g][ks * 8 + t];
                af[mt][1] = As[row + g + 8][ks * 8 + t];
                af[mt][2] = As[row + g][ks * 8 + t + 4];
                af[mt][3] = As[row + g + 8][ks * 8 + t + 4];
            }
            uint32_t bf[8][2];
#pragma unroll
            for (int nt = 0; nt < 8; nt++) {
                int col = wn * 64 + nt * 8 + g;
                bf[nt][0] = Bs[ks * 8 + t][col];
                bf[nt][1] = Bs[ks * 8 + t + 4][col];
            }
#pragma unroll
            for (int mt = 0; mt < 2; mt++)
#pragma unroll
                for (int nt = 0; nt < 8; nt++)
                    mma_tf32(acc[mt][nt], af[mt], bf[nt]);
        }
        __syncthreads();
    }

    // epilogue
#pragma unroll
    for (int mt = 0; mt < 2; mt++) {
        int row0 = by * 128 + wm * 32 + mt * 16 + g;
#pragma unroll
        for (int nt = 0; nt < 8; nt++) {
            int col = bx * 128 + wn * 64 + nt * 8 + 2 * t;
            float2 v0 = make_float2(acc[mt][nt][0], acc[mt][nt][1]);
            float2 v1 = make_float2(acc[mt][nt][2], acc[mt][nt][3]);
            *(float2*)(C + (size_t)row0 * N + col) = v0;
            *(float2*)(C + (size_t)(row0 + 8) * N + col) = v1;
        }
    }
}

// ---------------------------------------------------------------------------
// Flash attention (causal), tf32 tensor cores.
// Block: 128 threads (4 warps). Q tile 64 rows, K tile 64, DH=64.
// Warp w owns query rows [16w, 16w+16). Online softmax on C fragments.
// Smem (floats): Qs[64][68], Ks[64][68], Vs[64][72], Ps[64][68].
// ---------------------------------------------------------------------------
#define QS_OFF 0
#define KS_OFF 4352
#define VS_OFF 8704
#define PS_OFF 13312
#define FLASH_SMEM_B (17664 * 4)   // 70656 bytes

__global__ __launch_bounds__(128) void flash_attn_tf32(const float* __restrict__ qkv,
                                                       float* __restrict__ out)
{
    extern __shared__ float sm[];
    float* Qs = sm + QS_OFF;   // stride 68
    float* Ks = sm + KS_OFF;   // stride 68
    float* Vs = sm + VS_OFF;   // stride 72
    float* Ps = sm + PS_OFF;   // stride 68

    const float LOG2E = 1.44269504088896f;

    int qi = blockIdx.x;           // query tile 0..31
    int bh = blockIdx.y;           // 0..63
    int b = bh >> 4, h = bh & 15;
    int tid = threadIdx.x;
    int w = tid >> 5, lane = tid & 31;
    int g = lane >> 2, t = lane & 3;

    const float* qb = qkv + ((size_t)b * TT) * 3 * DD + h * DHH;
    const float* kb = qb + DD;
    const float* vb = qb + 2 * DD;
    int q0 = qi * 64;

    int lr = tid >> 1;             // loader row 0..63
    int lc = (tid & 1) * 32;       // loader col base

    // ---- load Q tile (pre-scaled by 1/8, tf32-rounded) ----
    {
        const float4* src = (const float4*)(qb + (size_t)(q0 + lr) * 3 * DD + lc);
#pragma unroll
        for (int i = 0; i < 8; i++) {
            float4 v = src[i];
            Qs[lr * 68 + lc + 4 * i + 0] = tf32f(v.x * 0.125f);
            Qs[lr * 68 + lc + 4 * i + 1] = tf32f(v.y * 0.125f);
            Qs[lr * 68 + lc + 4 * i + 2] = tf32f(v.z * 0.125f);
            Qs[lr * 68 + lc + 4 * i + 3] = tf32f(v.w * 0.125f);
        }
    }
    __syncwarp();   // Q rows [16w,16w+16) are written and read by warp w only

    // hoist Q A-fragments (invariant across key tiles)
    uint32_t af[8][4];
#pragma unroll
    for (int ks = 0; ks < 8; ks++) {
        int qrow = w * 16;
        af[ks][0] = __float_as_uint(Qs[(qrow + g) * 68 + ks * 8 + t]);
        af[ks][1] = __float_as_uint(Qs[(qrow + g + 8) * 68 + ks * 8 + t]);
        af[ks][2] = __float_as_uint(Qs[(qrow + g) * 68 + ks * 8 + t + 4]);
        af[ks][3] = __float_as_uint(Qs[(qrow + g + 8) * 68 + ks * 8 + t + 4]);
    }

    float O[8][4];
#pragma unroll
    for (int nt = 0; nt < 8; nt++)
#pragma unroll
        for (int i = 0; i < 4; i++) O[nt][i] = 0.f;
    float mx0 = -INFINITY, mx1 = -INFINITY;
    float ls0 = 0.f, ls1 = 0.f;

    for (int j = 0; j <= qi; j++) {
        __syncthreads();   // protect K/V/P from previous iteration
        // ---- load K,V tile ----
        {
            const float4* ks = (const float4*)(kb + (size_t)(j * 64 + lr) * 3 * DD + lc);
            const float4* vs = (const float4*)(vb + (size_t)(j * 64 + lr) * 3 * DD + lc);
#pragma unroll
            for (int i = 0; i < 8; i++) {
                float4 kv = ks[i];
                Ks[lr * 68 + lc + 4 * i + 0] = tf32f(kv.x);
                Ks[lr * 68 + lc + 4 * i + 1] = tf32f(kv.y);
                Ks[lr * 68 + lc + 4 * i + 2] = tf32f(kv.z);
                Ks[lr * 68 + lc + 4 * i + 3] = tf32f(kv.w);
                float4 vv = vs[i];
                Vs[lr * 72 + lc + 4 * i + 0] = tf32f(vv.x);
                Vs[lr * 72 + lc + 4 * i + 1] = tf32f(vv.y);
                Vs[lr * 72 + lc + 4 * i + 2] = tf32f(vv.z);
                Vs[lr * 72 + lc + 4 * i + 3] = tf32f(vv.w);
            }
        }
        __syncthreads();

        // ---- S = Q @ K^T  (scores already scaled via Q) ----
        float S[8][4];
#pragma unroll
        for (int nt = 0; nt < 8; nt++)
#pragma unroll
            for (int i = 0; i < 4; i++) S[nt][i] = 0.f;
#pragma unroll
        for (int nt = 0; nt < 8; nt++) {
#pragma unroll
            for (int ks = 0; ks < 8; ks++) {
                uint32_t bf[2];
                bf[0] = __float_as_uint(Ks[(nt * 8 + g) * 68 + ks * 8 + t]);
                bf[1] = __float_as_uint(Ks[(nt * 8 + g) * 68 + ks * 8 + t + 4]);
                mma_tf32(S[nt], af[ks], bf);
            }
        }

        // ---- causal mask on diagonal tile ----
        if (j == qi) {
            int r0l = w * 16 + g;
#pragma unroll
            for (int nt = 0; nt < 8; nt++) {
                int c0g = nt * 8 + 2 * t;
                if (c0g > r0l)         S[nt][0] = -INFINITY;
                if (c0g + 1 > r0l)     S[nt][1] = -INFINITY;
                if (c0g > r0l + 8)     S[nt][2] = -INFINITY;
                if (c0g + 1 > r0l + 8) S[nt][3] = -INFINITY;
            }
        }

        // ---- online softmax ----
        float rm0 = -INFINITY, rm1 = -INFINITY;
#pragma unroll
        for (int nt = 0; nt < 8; nt++) {
            rm0 = fmaxf(rm0, fmaxf(S[nt][0], S[nt][1]));
            rm1 = fmaxf(rm1, fmaxf(S[nt][2], S[nt][3]));
        }
        rm0 = fmaxf(rm0, __shfl_xor_sync(0xffffffffu, rm0, 1));
        rm0 = fmaxf(rm0, __shfl_xor_sync(0xffffffffu, rm0, 2));
        rm1 = fmaxf(rm1, __shfl_xor_sync(0xffffffffu, rm1, 1));
        rm1 = fmaxf(rm1, __shfl_xor_sync(0xffffffffu, rm1, 2));

        float mn0 = fmaxf(mx0, rm0);
        float mn1 = fmaxf(mx1, rm1);
        float a0 = exp2f((mx0 - mn0) * LOG2E);
        float a1 = exp2f((mx1 - mn1) * LOG2E);
        mx0 = mn0; mx1 = mn1;

        float s0 = 0.f, s1 = 0.f;
        int prow0 = (w * 16 + g) * 68;
        int prow1 = (w * 16 + g + 8) * 68;
#pragma unroll
        for (int nt = 0; nt < 8; nt++) {
            int pc = nt * 8 + 2 * t;
            float p00 = exp2f((S[nt][0] - mn0) * LOG2E);
            float p01 = exp2f((S[nt][1] - mn0) * LOG2E);
            float p10 = exp2f((S[nt][2] - mn1) * LOG2E);
            float p11 = exp2f((S[nt][3] - mn1) * LOG2E);
            s0 += p00 + p01;
            s1 += p10 + p11;
            *(float2*)(Ps + prow0 + pc) = make_float2(tf32f(p00), tf32f(p01));
            *(float2*)(Ps + prow1 + pc) = make_float2(tf32f(p10), tf32f(p11));
        }
        s0 += __shfl_xor_sync(0xffffffffu, s0, 1);
        s0 += __shfl_xor_sync(0xffffffffu, s0, 2);
        s1 += __shfl_xor_sync(0xffffffffu, s1, 1);
        s1 += __shfl_xor_sync(0xffffffffu, s1, 2);
        ls0 = ls0 * a0 + s0;
        ls1 = ls1 * a1 + s1;

#pragma unroll
        for (int nt = 0; nt < 8; nt++) {
            O[nt][0] *= a0; O[nt][1] *= a0;
            O[nt][2] *= a1; O[nt][3] *= a1;
        }
        __syncwarp();   // P rows are warp-private; order writes before frag reads

        // ---- O += P @ V ----
#pragma unroll
        for (int ks = 0; ks < 8; ks++) {
            uint32_t pa[4];
            pa[0] = __float_as_uint(Ps[(w * 16 + g) * 68 + ks * 8 + t]);
            pa[1] = __float_as_uint(Ps[(w * 16 + g + 8) * 68 + ks * 8 + t]);
            pa[2] = __float_as_uint(Ps[(w * 16 + g) * 68 + ks * 8 + t + 4]);
            pa[3] = __float_as_uint(Ps[(w * 16 + g + 8) * 68 + ks * 8 + t + 4]);
#pragma unroll
            for (int nt = 0; nt < 8; nt++) {
                uint32_t vf[2];
                vf[0] = __float_as_uint(Vs[(ks * 8 + t) * 72 + nt * 8 + g]);
                vf[1] = __float_as_uint(Vs[(ks * 8 + t + 4) * 72 + nt * 8 + g]);
                mma_tf32(O[nt], pa, vf);
            }
        }
    }

    // ---- finalize ----
    float il0 = 1.f / ls0, il1 = 1.f / ls1;
    int row0 = q0 + w * 16 + g;
    float* o0 = out + ((size_t)b * TT + row0) * DD + h * DHH;
    float* o1 = out + ((size_t)b * TT + row0 + 8) * DD + h * DHH;
#pragma unroll
    for (int nt = 0; nt < 8; nt++) {
        int col = nt * 8 + 2 * t;
        *(float2*)(o0 + col) = make_float2(O[nt][0] * il0, O[nt][1] * il0);
        *(float2*)(o1 + col) = make_float2(O[nt][2] * il1, O[nt][3] * il1);
    }
}

// ---------------------------------------------------------------------------
extern "C" void kernel_launch(void* const* d_in, const int* in_sizes, int n_in,
                              void* d_out, int out_size)
{
    const float* x    = (const float*)d_in[0];
    // d_in[1] = causal mask (structural; ignored)
    const float* Wqkv = (const float*)d_in[2];
    const float* Wout = (const float*)d_in[3];
    float* out = (float*)d_out;

    float* qkv_ptr  = nullptr;
    float* attn_ptr = nullptr;
    cudaGetSymbolAddress((void**)&qkv_ptr,  g_qkv);
    cudaGetSymbolAddress((void**)&attn_ptr, g_attn);

    cudaFuncSetAttribute(flash_attn_tf32, cudaFuncAttributeMaxDynamicSharedMemorySize,
                         FLASH_SMEM_B);

    const int M = BB * TT;        // 8192
    // 1) QKV projection: (8192,1024) @ (1024,3072)
    {
        dim3 grid(3 * DD / 128, M / 128);
        gemm_tf32<<<grid, 256>>>(x, Wqkv, qkv_ptr, M, 3 * DD, DD);
    }
    // 2) Flash attention (tf32 tensor cores)
    {
        dim3 grid(TT / 64, BB * HH);
        flash_attn_tf32<<<grid, 128, FLASH_SMEM_B>>>(qkv_ptr, attn_ptr);
    }
    // 3) Output projection: (8192,1024) @ (1024,1024)
    {
        dim3 grid(DD / 128, M / 128);
        gemm_tf32<<<grid, 256>>>(attn_ptr, Wout, out, M, DD, DD);
    }
}

// round 14
// speedup vs baseline: 3.8607x; 1.1159x over previous
#include <cuda_runtime.h>
#include <cuda_bf16.h>
#include <math.h>
#include <stdint.h>

// Problem constants
#define BB 4
#define TT 2048
#define DD 1024
#define HH 16
#define DHH 64

// Scratch buffers (no cudaMalloc allowed)
__device__ float g_qkv[(size_t)BB * TT * 3 * DD];   // (B,T,3D)
__device__ float g_attn[(size_t)BB * TT * DD];      // (B,T,D)

// ---------------------------------------------------------------------------
// tf32 helpers
// ---------------------------------------------------------------------------
__device__ __forceinline__ uint32_t tf32u(float x) {
    uint32_t u;
    asm("cvt.rna.tf32.f32 %0, %1;" : "=r"(u) : "f"(x));
    return u;
}
__device__ __forceinline__ float tf32f(float x) {
    return __uint_as_float(tf32u(x));
}

// mma.sync m16n8k8 tf32, fp32 accumulate (C += A*B)
__device__ __forceinline__ void mma_tf32(float* c, const uint32_t* a, const uint32_t* b) {
    asm volatile(
        "mma.sync.aligned.m16n8k8.row.col.f32.tf32.tf32.f32 "
        "{%0,%1,%2,%3}, {%4,%5,%6,%7}, {%8,%9}, {%0,%1,%2,%3};\n"
        : "+f"(c[0]), "+f"(c[1]), "+f"(c[2]), "+f"(c[3])
        : "r"(a[0]), "r"(a[1]), "r"(a[2]), "r"(a[3]), "r"(b[0]), "r"(b[1]));
}

// ---------------------------------------------------------------------------
// GEMM: C[M,N] = A[M,K] @ B[K,N], fp32 in/out, tf32 tensor-core compute.
// Block 128x128, BK=16, 256 threads (8 warps 4x2), warp tile 32x64.
// Fragment-packed double-buffered smem:
//   Af[stage][2048]: slot s = kb*256 + mb*32 + lane, 4 regs -> LDS.128 frags
//   Bf[stage][2048]: slot s = kb*512 + ntg*32 + lane, 2 regs -> LDS.64 frags
// Smem store address = slot * fragsize (slot = tid + 256*i). One sync/tile.
// ---------------------------------------------------------------------------
__global__ __launch_bounds__(256, 2) void gemm_tf32(const float* __restrict__ A,
                                                    const float* __restrict__ B,
                                                    float* __restrict__ C,
                                                    int M, int N, int K)
{
    __shared__ __align__(16) uint32_t Af[2][2048];
    __shared__ __align__(16) uint32_t Bf[2][2048];

    int tid = threadIdx.x;
    int warp = tid >> 5, lane = tid & 31;
    int g = lane >> 2, t = lane & 3;
    int wm = warp >> 1, wn = warp & 1;
    int bx = blockIdx.x, by = blockIdx.y;

    const float* Abase = A + (size_t)(by * 128) * K;
    const float* Bbase = B + bx * 128;

    // loader element offsets (relative to Abase/Bbase, advance per tile)
    uint32_t Aoff[2];
#pragma unroll
    for (int i = 0; i < 2; i++) {
        int s = tid + 256 * i;
        int kb = s >> 8, mb = (s >> 5) & 7, ln = s & 31;
        int lg = ln >> 2, lt = ln & 3;
        Aoff[i] = (uint32_t)((mb * 16 + lg) * K + kb * 8 + lt);
    }
    uint32_t Boff[4];
#pragma unroll
    for (int i = 0; i < 4; i++) {
        int s = tid + 256 * i;
        int kb = s >> 9, ntg = (s >> 5) & 15, ln = s & 31;
        int lg = ln >> 2, lt = ln & 3;
        Boff[i] = (uint32_t)((kb * 8 + lt) * N + ntg * 8 + lg);
    }

    float acc[2][8][4];
#pragma unroll
    for (int mt = 0; mt < 2; mt++)
#pragma unroll
        for (int nt = 0; nt < 8; nt++)
#pragma unroll
            for (int i = 0; i < 4; i++) acc[mt][nt][i] = 0.f;

    float pa[2][4], pb[4][2];
    const size_t K8 = (size_t)8 * K;
    const size_t N4 = (size_t)4 * N;

    // prologue: load + store tile 0
#pragma unroll
    for (int i = 0; i < 2; i++) {
        const float* p = Abase + Aoff[i];
        pa[i][0] = p[0]; pa[i][1] = p[K8]; pa[i][2] = p[4]; pa[i][3] = p[K8 + 4];
    }
#pragma unroll
    for (int i = 0; i < 4; i++) {
        const float* p = Bbase + Boff[i];
        pb[i][0] = p[0]; pb[i][1] = p[N4];
    }
#pragma unroll
    for (int i = 0; i < 2; i++) {
        uint4 v = make_uint4(tf32u(pa[i][0]), tf32u(pa[i][1]), tf32u(pa[i][2]), tf32u(pa[i][3]));
        *(uint4*)&Af[0][4 * (tid + 256 * i)] = v;
    }
#pragma unroll
    for (int i = 0; i < 4; i++) {
        uint2 v = make_uint2(tf32u(pb[i][0]), tf32u(pb[i][1]));
        *(uint2*)&Bf[0][2 * (tid + 256 * i)] = v;
    }
    __syncthreads();

    int ntile = K / 16;
    for (int kt = 0; kt < ntile; kt++) {
        int cur = kt & 1;
        bool hasNext = (kt + 1) < ntile;
        if (hasNext) {
            uint32_t ao = (uint32_t)((kt + 1) * 16);
#pragma unroll
            for (int i = 0; i < 2; i++) {
                const float* p = Abase + Aoff[i] + ao;
                pa[i][0] = p[0]; pa[i][1] = p[K8]; pa[i][2] = p[4]; pa[i][3] = p[K8 + 4];
            }
            size_t bo = (size_t)(kt + 1) * 16 * N;
#pragma unroll
            for (int i = 0; i < 4; i++) {
                const float* p = Bbase + Boff[i] + bo;
                pb[i][0] = p[0]; pb[i][1] = p[N4];
            }
        }

        // compute 2 k-steps from buf[cur]
#pragma unroll
        for (int kb = 0; kb < 2; kb++) {
            uint4 a0 = *(const uint4*)&Af[cur][((kb * 8 + wm * 2 + 0) * 32 + lane) * 4];
            uint4 a1 = *(const uint4*)&Af[cur][((kb * 8 + wm * 2 + 1) * 32 + lane) * 4];
            uint32_t af0[4] = {a0.x, a0.y, a0.z, a0.w};
            uint32_t af1[4] = {a1.x, a1.y, a1.z, a1.w};
#pragma unroll
            for (int nt = 0; nt < 8; nt++) {
                uint2 bv = *(const uint2*)&Bf[cur][((kb * 16 + wn * 8 + nt) * 32 + lane) * 2];
                uint32_t bfr[2] = {bv.x, bv.y};
                mma_tf32(acc[0][nt], af0, bfr);
                mma_tf32(acc[1][nt], af1, bfr);
            }
        }

        if (hasNext) {
            int nxt = cur ^ 1;
#pragma unroll
            for (int i = 0; i < 2; i++) {
                uint4 v = make_uint4(tf32u(pa[i][0]), tf32u(pa[i][1]), tf32u(pa[i][2]), tf32u(pa[i][3]));
                *(uint4*)&Af[nxt][4 * (tid + 256 * i)] = v;
            }
#pragma unroll
            for (int i = 0; i < 4; i++) {
                uint2 v = make_uint2(tf32u(pb[i][0]), tf32u(pb[i][1]));
                *(uint2*)&Bf[nxt][2 * (tid + 256 * i)] = v;
            }
        }
        __syncthreads();
    }

    // epilogue
#pragma unroll
    for (int mt = 0; mt < 2; mt++) {
        int row0 = by * 128 + wm * 32 + mt * 16 + g;
#pragma unroll
        for (int nt = 0; nt < 8; nt++) {
            int col = bx * 128 + wn * 64 + nt * 8 + 2 * t;
            *(float2*)(C + (size_t)row0 * N + col) = make_float2(acc[mt][nt][0], acc[mt][nt][1]);
            *(float2*)(C + (size_t)(row0 + 8) * N + col) = make_float2(acc[mt][nt][2], acc[mt][nt][3]);
        }
    }
}

// ---------------------------------------------------------------------------
// Flash attention (causal), tf32 tensor cores.
// Block: 256 threads (8 warps). Q tile 128 rows; warp w owns rows [16w,16w+16).
// K tile 64 keys. Packed K/V fragment smem (LDS.64 B-frags, conflict-free).
// Warp-level causal skip: fully-masked (warp, key-tile) pairs do no compute.
// Smem (floats): Qs[128*68]=8704, Ps[128*68]=8704, Kf[4096], Vf[4096]
//   -> 25600 floats = 102400 bytes.  (Kf/Vf: 64x64 tile = 2048 slots x 2.)
// ---------------------------------------------------------------------------
#define ATT_QS   0
#define ATT_PS   8704
#define ATT_KF   17408
#define ATT_VF   21504
#define ATT_SMEM_B (25600 * 4)   // 102400 bytes

__global__ __launch_bounds__(256, 2) void flash_attn_tf32(const float* __restrict__ qkv,
                                                          float* __restrict__ out)
{
    extern __shared__ float sm[];
    float* Qs = sm + ATT_QS;    // [128][68]
    float* Ps = sm + ATT_PS;    // [128][68]
    float* Kf = sm + ATT_KF;    // packed [8][8][32][2] = 4096 floats
    float* Vf = sm + ATT_VF;    // packed [8][8][32][2] = 4096 floats

    const float LOG2E = 1.44269504088896f;

    int qi = (TT / 128 - 1) - blockIdx.x;   // heavy tiles first
    int bh = blockIdx.y;                    // 0..63
    int b = bh >> 4, h = bh & 15;
    int tid = threadIdx.x;
    int w = tid >> 5, lane = tid & 31;
    int g = lane >> 2, t = lane & 3;

    const float* qb = qkv + ((size_t)b * TT) * 3 * DD + h * DHH;
    const float* kb = qb + DD;
    const float* vb = qb + 2 * DD;
    int q0 = qi * 128;

    // ---- load Q tile (pre-scaled by 1/8, tf32-rounded); rows are warp-private
    {
        int lr = tid >> 1, lc = (tid & 1) * 32;
        const float4* src = (const float4*)(qb + (size_t)(q0 + lr) * 3 * DD + lc);
        float* dst = Qs + lr * 68 + lc;
#pragma unroll
        for (int i = 0; i < 8; i++) {
            float4 v = src[i];
            dst[4 * i + 0] = tf32f(v.x * 0.125f);
            dst[4 * i + 1] = tf32f(v.y * 0.125f);
            dst[4 * i + 2] = tf32f(v.z * 0.125f);
            dst[4 * i + 3] = tf32f(v.w * 0.125f);
        }
    }
    __syncwarp();

    // K/V loader offsets: slot s = tid + 256*i, i<8.
    //  decode: kpart = s>>8, nt = (s>>5)&7, ln = s&31 (lg=ln>>2, lt=ln&3)
    //  Kf[kpart][nt][ln][p] = K[token nt*8+lg][feat kpart*8+lt+4p]
    //  Vf[kpart][nt][ln][p] = V[token kpart*8+lt+4p][dh nt*8+lg]
    //  smem dst offset = 2*s.
    uint32_t Koffs[8], Voffs[8];
#pragma unroll
    for (int i = 0; i < 8; i++) {
        int s = tid + 256 * i;
        int kpart = s >> 8, nt = (s >> 5) & 7, ln = s & 31;
        int lg = ln >> 2, lt = ln & 3;
        Koffs[i] = (uint32_t)((nt * 8 + lg) * 3 * DD + kpart * 8 + lt);
        Voffs[i] = (uint32_t)((kpart * 8 + lt) * 3 * DD + nt * 8 + lg);
    }

    float O[8][4];
#pragma unroll
    for (int nt = 0; nt < 8; nt++)
#pragma unroll
        for (int i = 0; i < 4; i++) O[nt][i] = 0.f;
    float mx0 = -INFINITY, mx1 = -INFINITY;
    float ls0 = 0.f, ls1 = 0.f;

    int qrow0 = q0 + w * 16;
    int jmax = 2 * qi + 1;

    for (int j = 0; j <= jmax; j++) {
        __syncthreads();   // protect K/V from previous iteration
        // ---- load K,V tile (packed fragments) ----
        {
            uint32_t jb = (uint32_t)(j * 64 * 3 * DD);
#pragma unroll
            for (int i = 0; i < 8; i++) {
                const float* kp = kb + Koffs[i] + jb;
                const float* vp = vb + Voffs[i] + jb;
                float k0 = kp[0], k1 = kp[4];
                float v0 = vp[0], v1 = vp[4 * 3 * DD];
                float* kd = Kf + 2 * (tid + 256 * i);
                float* vd = Vf + 2 * (tid + 256 * i);
                kd[0] = tf32f(k0); kd[1] = tf32f(k1);
                vd[0] = tf32f(v0); vd[1] = tf32f(v1);
            }
        }
        __syncthreads();

        int rel = qrow0 - j * 64;
        if (rel >= 0) {    // warp has at least one unmasked key in this tile
            // ---- S = Q @ K^T (scores pre-scaled via Q) ----
            float S[8][4];
#pragma unroll
            for (int nt = 0; nt < 8; nt++)
#pragma unroll
                for (int i = 0; i < 4; i++) S[nt][i] = 0.f;
#pragma unroll
            for (int ks = 0; ks < 8; ks++) {
                const float* qr = Qs + (w * 16) * 68 + ks * 8;
                uint32_t af[4];
                af[0] = __float_as_uint(qr[(g) * 68 + t]);
                af[1] = __float_as_uint(qr[(g + 8) * 68 + t]);
                af[2] = __float_as_uint(qr[(g) * 68 + t + 4]);
                af[3] = __float_as_uint(qr[(g + 8) * 68 + t + 4]);
#pragma unroll
                for (int nt = 0; nt < 8; nt++) {
                    uint2 bv = *(const uint2*)(Kf + ((ks * 8 + nt) * 32 + lane) * 2);
                    uint32_t bfr[2] = {bv.x, bv.y};
                    mma_tf32(S[nt], af, bfr);
                }
            }

            // ---- causal mask (diagonal tiles only) ----
            if (rel < 63) {
                int rr0 = rel + g;
                int rr1 = rel + g + 8;
#pragma unroll
                for (int nt = 0; nt < 8; nt++) {
                    int c0 = nt * 8 + 2 * t;
                    if (c0 > rr0)     S[nt][0] = -INFINITY;
                    if (c0 + 1 > rr0) S[nt][1] = -INFINITY;
                    if (c0 > rr1)     S[nt][2] = -INFINITY;
                    if (c0 + 1 > rr1) S[nt][3] = -INFINITY;
                }
            }

            // ---- online softmax ----
            float rm0 = -INFINITY, rm1 = -INFINITY;
#pragma unroll
            for (int nt = 0; nt < 8; nt++) {
                rm0 = fmaxf(rm0, fmaxf(S[nt][0], S[nt][1]));
                rm1 = fmaxf(rm1, fmaxf(S[nt][2], S[nt][3]));
            }
            rm0 = fmaxf(rm0, __shfl_xor_sync(0xffffffffu, rm0, 1));
            rm0 = fmaxf(rm0, __shfl_xor_sync(0xffffffffu, rm0, 2));
            rm1 = fmaxf(rm1, __shfl_xor_sync(0xffffffffu, rm1, 1));
            rm1 = fmaxf(rm1, __shfl_xor_sync(0xffffffffu, rm1, 2));

            float mn0 = fmaxf(mx0, rm0);
            float mn1 = fmaxf(mx1, rm1);
            float a0 = exp2f((mx0 - mn0) * LOG2E);
            float a1 = exp2f((mx1 - mn1) * LOG2E);
            mx0 = mn0; mx1 = mn1;

            float s0 = 0.f, s1 = 0.f;
            int prow0 = (w * 16 + g) * 68;
            int prow1 = (w * 16 + g + 8) * 68;
#pragma unroll
            for (int nt = 0; nt < 8; nt++) {
                int pc = nt * 8 + 2 * t;
                float p00 = exp2f((S[nt][0] - mn0) * LOG2E);
                float p01 = exp2f((S[nt][1] - mn0) * LOG2E);
                float p10 = exp2f((S[nt][2] - mn1) * LOG2E);
                float p11 = exp2f((S[nt][3] - mn1) * LOG2E);
                s0 += p00 + p01;
                s1 += p10 + p11;
                *(float2*)(Ps + prow0 + pc) = make_float2(tf32f(p00), tf32f(p01));
                *(float2*)(Ps + prow1 + pc) = make_float2(tf32f(p10), tf32f(p11));
            }
            s0 += __shfl_xor_sync(0xffffffffu, s0, 1);
            s0 += __shfl_xor_sync(0xffffffffu, s0, 2);
            s1 += __shfl_xor_sync(0xffffffffu, s1, 1);
            s1 += __shfl_xor_sync(0xffffffffu, s1, 2);
            ls0 = ls0 * a0 + s0;
            ls1 = ls1 * a1 + s1;

#pragma unroll
            for (int nt = 0; nt < 8; nt++) {
                O[nt][0] *= a0; O[nt][1] *= a0;
                O[nt][2] *= a1; O[nt][3] *= a1;
            }
            __syncwarp();   // P rows warp-private: order writes before frag reads

            // ---- O += P @ V ----
#pragma unroll
            for (int ks = 0; ks < 8; ks++) {
                uint32_t pa[4];
                pa[0] = __float_as_uint(Ps[(w * 16 + g) * 68 + ks * 8 + t]);
                pa[1] = __float_as_uint(Ps[(w * 16 + g + 8) * 68 + ks * 8 + t]);
                pa[2] = __float_as_uint(Ps[(w * 16 + g) * 68 + ks * 8 + t + 4]);
                pa[3] = __float_as_uint(Ps[(w * 16 + g + 8) * 68 + ks * 8 + t + 4]);
#pragma unroll
                for (int nt = 0; nt < 8; nt++) {
                    uint2 vv = *(const uint2*)(Vf + ((ks * 8 + nt) * 32 + lane) * 2);
                    uint32_t vfr[2] = {vv.x, vv.y};
                    mma_tf32(O[nt], pa, vfr);
                }
            }
        }
    }

    // ---- finalize ----
    float il0 = 1.f / ls0, il1 = 1.f / ls1;
    int row0 = q0 + w * 16 + g;
    float* o0 = out + ((size_t)b * TT + row0) * DD + h * DHH;
    float* o1 = out + ((size_t)b * TT + row0 + 8) * DD + h * DHH;
#pragma unroll
    for (int nt = 0; nt < 8; nt++) {
        int col = nt * 8 + 2 * t;
        *(float2*)(o0 + col) = make_float2(O[nt][0] * il0, O[nt][1] * il0);
        *(float2*)(o1 + col) = make_float2(O[nt][2] * il1, O[nt][3] * il1);
    }
}

// ---------------------------------------------------------------------------
extern "C" void kernel_launch(void* const* d_in, const int* in_sizes, int n_in,
                              void* d_out, int out_size)
{
    const float* x    = (const float*)d_in[0];
    // d_in[1] = causal mask (structural; ignored)
    const float* Wqkv = (const float*)d_in[2];
    const float* Wout = (const float*)d_in[3];
    float* out = (float*)d_out;

    float* qkv_ptr  = nullptr;
    float* attn_ptr = nullptr;
    cudaGetSymbolAddress((void**)&qkv_ptr,  g_qkv);
    cudaGetSymbolAddress((void**)&attn_ptr, g_attn);

    cudaFuncSetAttribute(flash_attn_tf32, cudaFuncAttributeMaxDynamicSharedMemorySize,
                         ATT_SMEM_B);

    const int M = BB * TT;        // 8192
    // 1) QKV projection: (8192,1024) @ (1024,3072)
    {
        dim3 grid(3 * DD / 128, M / 128);
        gemm_tf32<<<grid, 256>>>(x, Wqkv, qkv_ptr, M, 3 * DD, DD);
    }
    // 2) Flash attention (tf32 tensor cores)
    {
        dim3 grid(TT / 128, BB * HH);
        flash_attn_tf32<<<grid, 256, ATT_SMEM_B>>>(qkv_ptr, attn_ptr);
    }
    // 3) Output projection: (8192,1024) @ (1024,1024)
    {
        dim3 grid(DD / 128, M / 128);
        gemm_tf32<<<grid, 256>>>(attn_ptr, Wout, out, M, DD, DD);
    }
}

// round 16
// speedup vs baseline: 6.2603x; 1.6216x over previous
#include <cuda_runtime.h>
#include <cuda_fp16.h>
#include <cuda_bf16.h>
#include <math.h>
#include <stdint.h>

// Problem constants
#define BB 4
#define TT 2048
#define DD 1024
#define HH 16
#define DHH 64

// Scratch buffers (no cudaMalloc allowed)
__device__ float  g_qkv[(size_t)BB * TT * 3 * DD];   // (B,T,3D)
__device__ float  g_attn[(size_t)BB * TT * DD];      // (B,T,D)
__device__ __half g_WqkvT[(size_t)3 * DD * DD];      // [3072][1024] half, transposed
__device__ __half g_WoutT[(size_t)DD * DD];          // [1024][1024] half, transposed

// ---------------------------------------------------------------------------
// helpers
// ---------------------------------------------------------------------------
__device__ __forceinline__ uint32_t packh2(float lo, float hi) {
    __half2 h = __floats2half2_rn(lo, hi);
    return *(uint32_t*)&h;
}

// mma.sync m16n8k16 fp16 in, fp32 accumulate (C += A*B)
__device__ __forceinline__ void mma_f16(float* c, const uint32_t* a, const uint32_t* b) {
    asm volatile(
        "mma.sync.aligned.m16n8k16.row.col.f32.f16.f16.f32 "
        "{%0,%1,%2,%3}, {%4,%5,%6,%7}, {%8,%9}, {%0,%1,%2,%3};\n"
        : "+f"(c[0]), "+f"(c[1]), "+f"(c[2]), "+f"(c[3])
        : "r"(a[0]), "r"(a[1]), "r"(a[2]), "r"(a[3]), "r"(b[0]), "r"(b[1]));
}

// ---------------------------------------------------------------------------
// Weight transpose + fp16 convert: W[K][N] fp32 -> Wt[N][K] half
// ---------------------------------------------------------------------------
__global__ __launch_bounds__(256) void transpose_h(const float* __restrict__ W,
                                                   __half* __restrict__ Wt,
                                                   int K, int N)
{
    __shared__ float tb[32][33];
    int tx = threadIdx.x, ty = threadIdx.y;
    int n0 = blockIdx.x * 32, k0 = blockIdx.y * 32;
#pragma unroll
    for (int j = 0; j < 32; j += 8)
        tb[ty + j][tx] = W[(size_t)(k0 + ty + j) * N + n0 + tx];
    __syncthreads();
#pragma unroll
    for (int j = 0; j < 32; j += 8)
        Wt[(size_t)(n0 + ty + j) * K + k0 + tx] = __float2half_rn(tb[tx][ty + j]);
}

// ---------------------------------------------------------------------------
// fp16 GEMM: C[M,N] = A[M,K](fp32) @ WT[N,K](half)^T, fp32 out.
// Block 128x128, BK=32, 256 threads (8 warps 4x2), warp tile 32x64.
// Smem rows padded to 40 halves (80B): frag banks (20g + t) % 32 all-distinct.
// Single buffer, register prefetch, 2 syncs/tile (R6-proven skeleton).
// ---------------------------------------------------------------------------
__global__ __launch_bounds__(256, 2) void gemm_f16(const float* __restrict__ A,
                                                   const __half* __restrict__ Bt,
                                                   float* __restrict__ C,
                                                   int M, int N, int K)
{
    __shared__ __align__(16) __half Ah[128 * 40];
    __shared__ __align__(16) __half Bh[128 * 40];

    int tid = threadIdx.x;
    int warp = tid >> 5, lane = tid & 31;
    int g = lane >> 2, t = lane & 3;
    int wm = warp >> 1, wn = warp & 1;
    int bx = blockIdx.x, by = blockIdx.y;

    // loaders: 128 rows x 2 chunks of 16 halves
    int lrow = tid >> 1;
    int lc16 = (tid & 1) * 16;
    const float*  Ap = A + (size_t)(by * 128 + lrow) * K + lc16;
    const __half* Bp = Bt + (size_t)(bx * 128 + lrow) * K + lc16;

    float acc[2][8][4];
#pragma unroll
    for (int mt = 0; mt < 2; mt++)
#pragma unroll
        for (int nt = 0; nt < 8; nt++)
#pragma unroll
            for (int i = 0; i < 4; i++) acc[mt][nt][i] = 0.f;

    uint32_t nA[8];
    uint4 nB0, nB1;
    // preload tile 0
    {
        float4 f0 = *(const float4*)(Ap);
        float4 f1 = *(const float4*)(Ap + 4);
        float4 f2 = *(const float4*)(Ap + 8);
        float4 f3 = *(const float4*)(Ap + 12);
        nA[0] = packh2(f0.x, f0.y); nA[1] = packh2(f0.z, f0.w);
        nA[2] = packh2(f1.x, f1.y); nA[3] = packh2(f1.z, f1.w);
        nA[4] = packh2(f2.x, f2.y); nA[5] = packh2(f2.z, f2.w);
        nA[6] = packh2(f3.x, f3.y); nA[7] = packh2(f3.z, f3.w);
        nB0 = *(const uint4*)(Bp);
        nB1 = *(const uint4*)(Bp + 8);
    }

    const int NT = K / 32;
    for (int kt = 0; kt < NT; kt++) {
        // store prefetched tile
        *(uint4*)&Ah[lrow * 40 + lc16]     = make_uint4(nA[0], nA[1], nA[2], nA[3]);
        *(uint4*)&Ah[lrow * 40 + lc16 + 8] = make_uint4(nA[4], nA[5], nA[6], nA[7]);
        *(uint4*)&Bh[lrow * 40 + lc16]     = nB0;
        *(uint4*)&Bh[lrow * 40 + lc16 + 8] = nB1;
        __syncthreads();

        // prefetch next
        if (kt + 1 < NT) {
            const float* ap = Ap + (kt + 1) * 32;
            float4 f0 = *(const float4*)(ap);
            float4 f1 = *(const float4*)(ap + 4);
            float4 f2 = *(const float4*)(ap + 8);
            float4 f3 = *(const float4*)(ap + 12);
            nA[0] = packh2(f0.x, f0.y); nA[1] = packh2(f0.z, f0.w);
            nA[2] = packh2(f1.x, f1.y); nA[3] = packh2(f1.z, f1.w);
            nA[4] = packh2(f2.x, f2.y); nA[5] = packh2(f2.z, f2.w);
            nA[6] = packh2(f3.x, f3.y); nA[7] = packh2(f3.z, f3.w);
            const __half* bp = Bp + (kt + 1) * 32;
            nB0 = *(const uint4*)(bp);
            nB1 = *(const uint4*)(bp + 8);
        }

        // compute: 2 k-chunks of 16
#pragma unroll
        for (int kc = 0; kc < 2; kc++) {
            uint32_t af[2][4];
#pragma unroll
            for (int mt = 0; mt < 2; mt++) {
                int row = wm * 32 + mt * 16;
                af[mt][0] = *(const uint32_t*)&Ah[(row + g)     * 40 + kc * 16 + 2 * t];
                af[mt][1] = *(const uint32_t*)&Ah[(row + g + 8) * 40 + kc * 16 + 2 * t];
                af[mt][2] = *(const uint32_t*)&Ah[(row + g)     * 40 + kc * 16 + 2 * t + 8];
                af[mt][3] = *(const uint32_t*)&Ah[(row + g + 8) * 40 + kc * 16 + 2 * t + 8];
            }
#pragma unroll
            for (int nt = 0; nt < 8; nt++) {
                int col = wn * 64 + nt * 8 + g;
                uint32_t bf[2];
                bf[0] = *(const uint32_t*)&Bh[col * 40 + kc * 16 + 2 * t];
                bf[1] = *(const uint32_t*)&Bh[col * 40 + kc * 16 + 2 * t + 8];
                mma_f16(acc[0][nt], af[0], bf);
                mma_f16(acc[1][nt], af[1], bf);
            }
        }
        __syncthreads();
    }

    // epilogue
#pragma unroll
    for (int mt = 0; mt < 2; mt++) {
        int row0 = by * 128 + wm * 32 + mt * 16 + g;
#pragma unroll
        for (int nt = 0; nt < 8; nt++) {
            int col = bx * 128 + wn * 64 + nt * 8 + 2 * t;
            *(float2*)(C + (size_t)row0 * N + col) = make_float2(acc[mt][nt][0], acc[mt][nt][1]);
            *(float2*)(C + (size_t)(row0 + 8) * N + col) = make_float2(acc[mt][nt][2], acc[mt][nt][3]);
        }
    }
}

// ---------------------------------------------------------------------------
// Flash attention (causal), fp16 mma.sync m16n8k16.
// 256 threads (8 warps). Q tile 128 rows; warp w owns rows [16w,16w+16).
// Key tile 64. Q fragments loaded directly from global (no Q smem).
// P stays in registers (S-frag -> half2 pack -> A-frag). K needs no transpose;
// V transposed into smem [dh][key] rows padded to 72 halves.
// Smem: Ksm[64*72] + Vt[64*72] halves = 18432 B.
// ---------------------------------------------------------------------------
__global__ __launch_bounds__(256, 2) void flash_f16(const float* __restrict__ qkv,
                                                    float* __restrict__ out)
{
    __shared__ __align__(16) __half Ksm[64 * 72];
    __shared__ __align__(16) __half Vt[64 * 72];

    const float LOG2E = 1.44269504088896f;

    int qi = (TT / 128 - 1) - blockIdx.x;   // heavy tiles first
    int bh = blockIdx.y;                    // 0..63
    int b = bh >> 4, h = bh & 15;
    int tid = threadIdx.x;
    int w = tid >> 5, lane = tid & 31;
    int g = lane >> 2, t = lane & 3;

    const float* qb = qkv + ((size_t)b * TT) * 3 * DD + h * DHH;
    const float* kb = qb + DD;
    const float* vb = qb + 2 * DD;
    int q0 = qi * 128;
    int qrow0 = q0 + w * 16;

    // ---- Q fragments straight from global (pre-scaled 1/8) ----
    uint32_t qf[4][4];
#pragma unroll
    for (int kc = 0; kc < 4; kc++) {
        const float* r0 = qb + (size_t)(qrow0 + g) * 3 * DD + kc * 16 + 2 * t;
        const float* r1 = qb + (size_t)(qrow0 + g + 8) * 3 * DD + kc * 16 + 2 * t;
        float2 v00 = *(const float2*)(r0);
        float2 v10 = *(const float2*)(r1);
        float2 v01 = *(const float2*)(r0 + 8);
        float2 v11 = *(const float2*)(r1 + 8);
        qf[kc][0] = packh2(v00.x * 0.125f, v00.y * 0.125f);
        qf[kc][1] = packh2(v10.x * 0.125f, v10.y * 0.125f);
        qf[kc][2] = packh2(v01.x * 0.125f, v01.y * 0.125f);
        qf[kc][3] = packh2(v11.x * 0.125f, v11.y * 0.125f);
    }

    // K loader: 64 rows x 4 chunks of 16 halves; one slot per thread
    int krow = tid >> 2, kc16 = (tid & 3) * 16;
    // V loader: 8 slots; VT[dh][key] pairs; conflict-free STS (banks 4*lg+lt)
    uint32_t voff[8], vsts[8];
#pragma unroll
    for (int i = 0; i < 8; i++) {
        int s = tid + 256 * i;
        int ln = s & 31, lt = ln & 3, lg = ln >> 2;
        int mid = (s >> 5) & 7, top = s >> 8;
        int dh = mid * 8 + lg, kp = top * 4 + lt;
        voff[i] = (uint32_t)(2 * kp * 3 * DD + dh);
        vsts[i] = (uint32_t)(dh * 72 + 2 * kp);
    }

    float O[8][4];
#pragma unroll
    for (int nt = 0; nt < 8; nt++)
#pragma unroll
        for (int i = 0; i < 4; i++) O[nt][i] = 0.f;
    float mx0 = -INFINITY, mx1 = -INFINITY;
    float ls0 = 0.f, ls1 = 0.f;

    int jmax = 2 * qi + 1;
    for (int j = 0; j <= jmax; j++) {
        __syncthreads();   // protect K/V from previous iteration
        // ---- K tile: [key][dh] halves ----
        {
            const float* p = kb + (size_t)(j * 64 + krow) * 3 * DD + kc16;
            float4 f0 = *(const float4*)(p);
            float4 f1 = *(const float4*)(p + 4);
            float4 f2 = *(const float4*)(p + 8);
            float4 f3 = *(const float4*)(p + 12);
            *(uint4*)&Ksm[krow * 72 + kc16] =
                make_uint4(packh2(f0.x, f0.y), packh2(f0.z, f0.w),
                           packh2(f1.x, f1.y), packh2(f1.z, f1.w));
            *(uint4*)&Ksm[krow * 72 + kc16 + 8] =
                make_uint4(packh2(f2.x, f2.y), packh2(f2.z, f2.w),
                           packh2(f3.x, f3.y), packh2(f3.z, f3.w));
        }
        // ---- V tile transposed: VT[dh][key] ----
        {
            uint32_t jb = (uint32_t)(j * 64 * 3 * DD);
#pragma unroll
            for (int i = 0; i < 8; i++) {
                const float* vp = vb + voff[i] + jb;
                float v0 = vp[0];
                float v1 = vp[3 * DD];
                *(uint32_t*)&Vt[vsts[i]] = packh2(v0, v1);
            }
        }
        __syncthreads();

        int rel = qrow0 - j * 64;
        if (rel >= 0) {
            // ---- S = Q @ K^T ----
            float S[8][4];
#pragma unroll
            for (int nt = 0; nt < 8; nt++)
#pragma unroll
                for (int i = 0; i < 4; i++) S[nt][i] = 0.f;
#pragma unroll
            for (int kc = 0; kc < 4; kc++) {
#pragma unroll
                for (int nt = 0; nt < 8; nt++) {
                    uint32_t bf[2];
                    bf[0] = *(const uint32_t*)&Ksm[(nt * 8 + g) * 72 + kc * 16 + 2 * t];
                    bf[1] = *(const uint32_t*)&Ksm[(nt * 8 + g) * 72 + kc * 16 + 2 * t + 8];
                    mma_f16(S[nt], qf[kc], bf);
                }
            }

            // ---- causal mask (diagonal tiles only) ----
            if (rel < 63) {
                int rr0 = rel + g;
                int rr1 = rel + g + 8;
#pragma unroll
                for (int nt = 0; nt < 8; nt++) {
                    int c0 = nt * 8 + 2 * t;
                    if (c0 > rr0)     S[nt][0] = -INFINITY;
                    if (c0 + 1 > rr0) S[nt][1] = -INFINITY;
                    if (c0 > rr1)     S[nt][2] = -INFINITY;
                    if (c0 + 1 > rr1) S[nt][3] = -INFINITY;
                }
            }

            // ---- online softmax ----
            float rm0 = -INFINITY, rm1 = -INFINITY;
#pragma unroll
            for (int nt = 0; nt < 8; nt++) {
                rm0 = fmaxf(rm0, fmaxf(S[nt][0], S[nt][1]));
                rm1 = fmaxf(rm1, fmaxf(S[nt][2], S[nt][3]));
            }
            rm0 = fmaxf(rm0, __shfl_xor_sync(0xffffffffu, rm0, 1));
            rm0 = fmaxf(rm0, __shfl_xor_sync(0xffffffffu, rm0, 2));
            rm1 = fmaxf(rm1, __shfl_xor_sync(0xffffffffu, rm1, 1));
            rm1 = fmaxf(rm1, __shfl_xor_sync(0xffffffffu, rm1, 2));

            float mn0 = fmaxf(mx0, rm0);
            float mn1 = fmaxf(mx1, rm1);
            float a0 = exp2f((mx0 - mn0) * LOG2E);
            float a1 = exp2f((mx1 - mn1) * LOG2E);
            mx0 = mn0; mx1 = mn1;

            // P in registers: phA[nt] = rows g, phB[nt] = rows g+8
            uint32_t phA[8], phB[8];
            float s0 = 0.f, s1 = 0.f;
#pragma unroll
            for (int nt = 0; nt < 8; nt++) {
                float p00 = exp2f((S[nt][0] - mn0) * LOG2E);
                float p01 = exp2f((S[nt][1] - mn0) * LOG2E);
                float p10 = exp2f((S[nt][2] - mn1) * LOG2E);
                float p11 = exp2f((S[nt][3] - mn1) * LOG2E);
                s0 += p00 + p01;
                s1 += p10 + p11;
                phA[nt] = packh2(p00, p01);
                phB[nt] = packh2(p10, p11);
            }
            s0 += __shfl_xor_sync(0xffffffffu, s0, 1);
            s0 += __shfl_xor_sync(0xffffffffu, s0, 2);
            s1 += __shfl_xor_sync(0xffffffffu, s1, 1);
            s1 += __shfl_xor_sync(0xffffffffu, s1, 2);
            ls0 = ls0 * a0 + s0;
            ls1 = ls1 * a1 + s1;

#pragma unroll
            for (int nt = 0; nt < 8; nt++) {
                O[nt][0] *= a0; O[nt][1] *= a0;
                O[nt][2] *= a1; O[nt][3] *= a1;
            }

            // ---- O += P @ V  (P register-resident) ----
#pragma unroll
            for (int kc = 0; kc < 4; kc++) {
                uint32_t pa[4];
                pa[0] = phA[2 * kc];
                pa[1] = phB[2 * kc];
                pa[2] = phA[2 * kc + 1];
                pa[3] = phB[2 * kc + 1];
#pragma unroll
                for (int nt = 0; nt < 8; nt++) {
                    uint32_t vf[2];
                    vf[0] = *(const uint32_t*)&Vt[(nt * 8 + g) * 72 + kc * 16 + 2 * t];
                    vf[1] = *(const uint32_t*)&Vt[(nt * 8 + g) * 72 + kc * 16 + 2 * t + 8];
                    mma_f16(O[nt], pa, vf);
                }
            }
        }
    }

    // ---- finalize ----
    float il0 = 1.f / ls0, il1 = 1.f / ls1;
    int row0 = q0 + w * 16 + g;
    float* o0 = out + ((size_t)b * TT + row0) * DD + h * DHH;
    float* o1 = out + ((size_t)b * TT + row0 + 8) * DD + h * DHH;
#pragma unroll
    for (int nt = 0; nt < 8; nt++) {
        int col = nt * 8 + 2 * t;
        *(float2*)(o0 + col) = make_float2(O[nt][0] * il0, O[nt][1] * il0);
        *(float2*)(o1 + col) = make_float2(O[nt][2] * il1, O[nt][3] * il1);
    }
}

// ---------------------------------------------------------------------------
extern "C" void kernel_launch(void* const* d_in, const int* in_sizes, int n_in,
                              void* d_out, int out_size)
{
    const float* x    = (const float*)d_in[0];
    // d_in[1] = causal mask (structural; ignored)
    const float* Wqkv = (const float*)d_in[2];
    const float* Wout = (const float*)d_in[3];
    float* out = (float*)d_out;

    float*  qkv_ptr  = nullptr;
    float*  attn_ptr = nullptr;
    __half* wqkvT    = nullptr;
    __half* woutT    = nullptr;
    cudaGetSymbolAddress((void**)&qkv_ptr,  g_qkv);
    cudaGetSymbolAddress((void**)&attn_ptr, g_attn);
    cudaGetSymbolAddress((void**)&wqkvT,    g_WqkvT);
    cudaGetSymbolAddress((void**)&woutT,    g_WoutT);

    const int M = BB * TT;        // 8192

    // 0) Weight transposes (fp32 -> half, [N][K])
    {
        dim3 blk(32, 8);
        transpose_h<<<dim3(3 * DD / 32, DD / 32), blk>>>(Wqkv, wqkvT, DD, 3 * DD);
        transpose_h<<<dim3(DD / 32, DD / 32), blk>>>(Wout, woutT, DD, DD);
    }
    // 1) QKV projection: (8192,1024) @ (1024,3072)
    {
        dim3 grid(3 * DD / 128, M / 128);
        gemm_f16<<<grid, 256>>>(x, wqkvT, qkv_ptr, M, 3 * DD, DD);
    }
    // 2) Flash attention (fp16 mma.sync)
    {
        dim3 grid(TT / 128, BB * HH);
        flash_f16<<<grid, 256>>>(qkv_ptr, attn_ptr);
    }
    // 3) Output projection: (8192,1024) @ (1024,1024)
    {
        dim3 grid(DD / 128, M / 128);
        gemm_f16<<<grid, 256>>>(attn_ptr, woutT, out, M, DD, DD);
    }
}